// round 4
// baseline (speedup 1.0000x reference)
#include <cuda_runtime.h>

// TripletCenterLoss — collapsed to [B x NC] distances.
// B=8192, D=512, NC=55, margin=0.2. targets arrive as int32.
//
// Main kernel: S = X @ C^T with packed f32x2 FMA.
// Block = 256 threads = 2 K-halves x (8 m x 8 n), thread tile 4 rows x 7 classes.
// Grid = 256 blocks (32 rows each). K-halves combined in smem.
// Loss/prec finalized by last block (fenced atomic counter).

#define BB 8192
#define DD 512
#define NC 55
#define MARGINF 0.2f

__device__ float  g_cn[56];        // ||center_c||^2
__device__ int    g_present[56];   // class appears in targets
__device__ float2 g_partial[256];  // per-block (loss_sum, prec_sum)
__device__ int    g_done = 0;      // completion counter (self-resetting)

__device__ __forceinline__ void fma2(unsigned long long &d,
                                     unsigned long long a,
                                     unsigned long long b) {
    asm("fma.rn.f32x2 %0, %1, %2, %0;" : "+l"(d) : "l"(a), "l"(b));
}
__device__ __forceinline__ void add2(unsigned long long &d,
                                     unsigned long long a) {
    asm("add.rn.f32x2 %0, %0, %1;" : "+l"(d) : "l"(a));
}
__device__ __forceinline__ float lo32(unsigned long long v) {
    return __int_as_float((int)(unsigned)(v & 0xffffffffull));
}
__device__ __forceinline__ float hi32(unsigned long long v) {
    return __int_as_float((int)(unsigned)(v >> 32));
}

// ============================================================
// Prep: 56 blocks x 256 threads.
// Blocks 0..54: ||center_b||^2.  Block 55: present flags.
// ============================================================
__global__ void prep_kernel(const int* __restrict__ tgt,
                            const float* __restrict__ cen) {
    const int b = blockIdx.x;
    const int tid = threadIdx.x;

    if (b < NC) {
        const float2* p = (const float2*)(cen + (size_t)b * DD);
        float2 v = p[tid];                       // 256 x float2 = 512
        float s = v.x * v.x + v.y * v.y;
        #pragma unroll
        for (int o = 16; o; o >>= 1) s += __shfl_xor_sync(0xffffffffu, s, o);
        __shared__ float ws[8];
        if ((tid & 31) == 0) ws[tid >> 5] = s;
        __syncthreads();
        if (tid == 0) {
            float t = 0.0f;
            #pragma unroll
            for (int w = 0; w < 8; w++) t += ws[w];
            g_cn[b] = t;
        }
    } else {
        __shared__ int flags[64];
        if (tid < 64) flags[tid] = 0;
        __syncthreads();
        #pragma unroll 8
        for (int i = tid; i < BB; i += 256) flags[tgt[i]] = 1;
        __syncthreads();
        if (tid < 56) g_present[tid] = flags[tid];
        if (tid == 0) g_cn[55] = 0.0f;
    }
}

// ============================================================
// Main kernel
// ============================================================
__global__ __launch_bounds__(256, 2)
void tcl_main_kernel(const float* __restrict__ x,
                     const int* __restrict__ tgt,
                     const float* __restrict__ cen,
                     float* __restrict__ out) {
    const int tid = threadIdx.x;
    const int h  = tid >> 6;       // K-half: 0 or 1
    const int t  = tid & 63;
    const int mt = t >> 3;         // 0..7
    const int n  = t & 7;          // 0..7
    const int r0 = blockIdx.x * 32 + mt * 4;

    // pointers, offset by K-half (64 ulonglong2 = 256 floats)
    const ulonglong2* __restrict__ xr[4];
    #pragma unroll
    for (int i = 0; i < 4; i++)
        xr[i] = (const ulonglong2*)(x + (size_t)(r0 + i) * DD) + h * 64;

    int cls[7];
    const ulonglong2* __restrict__ cb[7];
    #pragma unroll
    for (int j = 0; j < 7; j++) {
        cls[j] = n * 7 + j;                        // 0..55 (55 = pad)
        int cc = cls[j] < NC ? cls[j] : NC - 1;
        cb[j] = (const ulonglong2*)(cen + (size_t)cc * DD) + h * 64;
    }

    unsigned long long acc[4][7], xn2[4];
    #pragma unroll
    for (int i = 0; i < 4; i++) {
        xn2[i] = 0ull;
        #pragma unroll
        for (int j = 0; j < 7; j++) acc[i][j] = 0ull;
    }

    // 64 k-steps of 4 floats each (half of D=512)
    #pragma unroll 2
    for (int k = 0; k < 64; k++) {
        ulonglong2 b[7];
        #pragma unroll
        for (int j = 0; j < 7; j++) b[j] = __ldg(cb[j] + k);
        #pragma unroll
        for (int i = 0; i < 4; i++) {
            ulonglong2 a = __ldg(xr[i] + k);
            fma2(xn2[i], a.x, a.x);
            fma2(xn2[i], a.y, a.y);
            #pragma unroll
            for (int j = 0; j < 7; j++) {
                fma2(acc[i][j], a.x, b[j].x);
                fma2(acc[i][j], a.y, b[j].y);
            }
        }
    }

    // ---- combine the two K-halves (conflict-free layout comb[w][t]) ----
    __shared__ unsigned long long comb[32][64];
    if (h == 1) {
        #pragma unroll
        for (int i = 0; i < 4; i++) {
            #pragma unroll
            for (int j = 0; j < 7; j++) comb[i * 7 + j][t] = acc[i][j];
            comb[28 + i][t] = xn2[i];
        }
    }
    __syncthreads();

    __shared__ float2 red[2];
    if (h == 0) {
        #pragma unroll
        for (int i = 0; i < 4; i++) {
            #pragma unroll
            for (int j = 0; j < 7; j++) add2(acc[i][j], comb[i * 7 + j][t]);
            add2(xn2[i], comb[28 + i][t]);
        }

        // ---- epilogue ----
        float cnv[7];
        int pres[7];
        #pragma unroll
        for (int j = 0; j < 7; j++) {
            if (cls[j] < NC) { cnv[j] = g_cn[cls[j]]; pres[j] = g_present[cls[j]]; }
            else             { cnv[j] = 0.0f;         pres[j] = 0; }
        }

        float lsum = 0.0f, psum = 0.0f;
        #pragma unroll
        for (int i = 0; i < 4; i++) {
            float xn = lo32(xn2[i]) + hi32(xn2[i]);
            int tg = tgt[r0 + i];
            float ap = -1e30f, an = 1e30f;
            #pragma unroll
            for (int j = 0; j < 7; j++) {
                if (!pres[j]) continue;
                float S = lo32(acc[i][j]) + hi32(acc[i][j]);
                float d2 = xn + cnv[j] - 2.0f * S;
                float d = sqrtf(fmaxf(d2, 1e-12f));
                if (cls[j] == tg) ap = d;
                else an = fminf(an, d);
            }
            #pragma unroll
            for (int o = 1; o < 8; o <<= 1) {
                ap = fmaxf(ap, __shfl_xor_sync(0xffffffffu, ap, o));
                an = fminf(an, __shfl_xor_sync(0xffffffffu, an, o));
            }
            if (n == 0) {
                lsum += fmaxf(ap - an + MARGINF, 0.0f);
                psum += (an > ap) ? 1.0f : 0.0f;
            }
        }
        // warp sum (non n==0 lanes hold 0)
        #pragma unroll
        for (int o = 16; o; o >>= 1) {
            lsum += __shfl_xor_sync(0xffffffffu, lsum, o);
            psum += __shfl_xor_sync(0xffffffffu, psum, o);
        }
        if ((t & 31) == 0) red[t >> 5] = make_float2(lsum, psum);
    }
    __syncthreads();

    // ---- publish block partial + last-block finalize ----
    __shared__ int lastflag;
    if (tid == 0) {
        g_partial[blockIdx.x] = make_float2(red[0].x + red[1].x,
                                            red[0].y + red[1].y);
        __threadfence();
        int old = atomicAdd(&g_done, 1);
        lastflag = (old == (int)gridDim.x - 1) ? 1 : 0;
    }
    __syncthreads();

    if (lastflag) {
        __shared__ float2 s[128];
        if (tid < 128) {
            float2 a = g_partial[tid];
            float2 b = g_partial[tid + 128];
            s[tid] = make_float2(a.x + b.x, a.y + b.y);
        }
        __syncthreads();
        #pragma unroll
        for (int o = 64; o; o >>= 1) {
            if (tid < o) { s[tid].x += s[tid + o].x; s[tid].y += s[tid + o].y; }
            __syncthreads();
        }
        if (tid == 0) {
            out[0] = s[0].x / (float)BB;   // loss
            out[1] = s[0].y / (float)BB;   // prec
            g_done = 0;                    // reset for next graph replay
        }
    }
}

extern "C" void kernel_launch(void* const* d_in, const int* in_sizes, int n_in,
                              void* d_out, int out_size) {
    const float* x   = (const float*)d_in[0];
    const int*   tgt = (const int*)d_in[1];
    const float* cen = (const float*)d_in[2];
    float* out = (float*)d_out;

    prep_kernel<<<56, 256>>>(tgt, cen);
    tcl_main_kernel<<<256, 256>>>(x, tgt, cen, out);
}

// round 5
// speedup vs baseline: 4.3076x; 4.3076x over previous
#include <cuda_runtime.h>

// TripletCenterLoss — collapsed to [B x NC] distances, smem-staged f32x2 GEMM.
// B=8192, D=512, NC=55, margin=0.2. targets arrive as int32.

#define BB 8192
#define DD 512
#define NC 55
#define MARGINF 0.2f

#define MBLK 32          // rows per block
#define KC 32            // k-chunk (floats)
#define NCHUNK (DD / KC) // 16
#define PAD 44           // smem row stride in floats (conflict-free, 16B-aligned)

__device__ float  g_cn[56];
__device__ int    g_present[56];
__device__ float2 g_partial[256];
__device__ int    g_done = 0;

__device__ __forceinline__ void fma2(unsigned long long &d,
                                     unsigned long long a,
                                     unsigned long long b) {
    asm("fma.rn.f32x2 %0, %1, %2, %0;" : "+l"(d) : "l"(a), "l"(b));
}
__device__ __forceinline__ float lo32(unsigned long long v) {
    return __int_as_float((int)(unsigned)(v & 0xffffffffull));
}
__device__ __forceinline__ float hi32(unsigned long long v) {
    return __int_as_float((int)(unsigned)(v >> 32));
}

// ============================================================
// Prep: 56 blocks x 256 threads.
// ============================================================
__global__ void prep_kernel(const int* __restrict__ tgt,
                            const float* __restrict__ cen) {
    const int b = blockIdx.x;
    const int tid = threadIdx.x;

    if (b < NC) {
        const float2* p = (const float2*)(cen + (size_t)b * DD);
        float2 v = p[tid];
        float s = v.x * v.x + v.y * v.y;
        #pragma unroll
        for (int o = 16; o; o >>= 1) s += __shfl_xor_sync(0xffffffffu, s, o);
        __shared__ float ws[8];
        if ((tid & 31) == 0) ws[tid >> 5] = s;
        __syncthreads();
        if (tid == 0) {
            float t = 0.0f;
            #pragma unroll
            for (int w = 0; w < 8; w++) t += ws[w];
            g_cn[b] = t;
        }
    } else {
        __shared__ int flags[64];
        if (tid < 64) flags[tid] = 0;
        __syncthreads();
        #pragma unroll 8
        for (int i = tid; i < BB; i += 256) flags[tgt[i]] = 1;
        __syncthreads();
        if (tid < 56) g_present[tid] = flags[tid];
        if (tid == 0) g_cn[55] = 0.0f;
    }
}

// ============================================================
// Main: grid 256 x 128 threads. M_blk=32, TM=2, TN=7.
// ============================================================
__global__ __launch_bounds__(128)
void tcl_main_kernel(const float* __restrict__ x,
                     const int* __restrict__ tgt,
                     const float* __restrict__ cen,
                     float* __restrict__ out) {
    __shared__ float xs[MBLK * PAD];   // 32 rows
    __shared__ float cs[56 * PAD];     // 56 classes (55 is pad, unwritten)

    const int tid = threadIdx.x;
    const int mt  = tid >> 3;          // 0..15
    const int n   = tid & 7;           // 0..7
    const int r0  = blockIdx.x * MBLK;

    // staging mapping: thread -> (row=tid>>3, k4=tid&7)
    const int srow = tid >> 3;         // 0..15 (and +16)
    const int sk4  = tid & 7;          // 0..7
    const float4* __restrict__ xg0 =
        (const float4*)(x + (size_t)(r0 + srow) * DD) + sk4;
    const float4* __restrict__ xg1 =
        (const float4*)(x + (size_t)(r0 + srow + 16) * DD) + sk4;
    // C staging: idx = tid + q*128, class = idx>>3, k4 = idx&7; 55*8=440 valid
    const int cidx0 = tid;

    // compute-phase smem pointers (16B aligned: PAD*4 = 176, k4*16)
    const ulonglong2* __restrict__ aptr[2];
    #pragma unroll
    for (int i = 0; i < 2; i++)
        aptr[i] = (const ulonglong2*)(xs + (mt * 2 + i) * PAD);
    int cls[7];
    const ulonglong2* __restrict__ bptr[7];
    #pragma unroll
    for (int j = 0; j < 7; j++) {
        cls[j] = n * 7 + j;
        bptr[j] = (const ulonglong2*)(cs + cls[j] * PAD);
    }

    unsigned long long acc[2][7], xn2[2];
    #pragma unroll
    for (int i = 0; i < 2; i++) {
        xn2[i] = 0ull;
        #pragma unroll
        for (int j = 0; j < 7; j++) acc[i][j] = 0ull;
    }

    // prefetch registers
    float4 px0, px1, pc[4];

    // ---- prefetch chunk 0 ----
    px0 = __ldg(xg0);
    px1 = __ldg(xg1);
    #pragma unroll
    for (int q = 0; q < 4; q++) {
        int idx = cidx0 + q * 128;
        if (idx < 440) {
            int cl = idx >> 3, k4 = idx & 7;
            pc[q] = __ldg((const float4*)(cen + (size_t)cl * DD) + k4);
        }
    }

    #pragma unroll 1
    for (int c = 0; c < NCHUNK; c++) {
        __syncthreads();   // prior compute done -> safe to overwrite smem
        // store staged chunk
        *(float4*)(xs + srow * PAD + sk4 * 4)        = px0;
        *(float4*)(xs + (srow + 16) * PAD + sk4 * 4) = px1;
        #pragma unroll
        for (int q = 0; q < 4; q++) {
            int idx = cidx0 + q * 128;
            if (idx < 440)
                *(float4*)(cs + (idx >> 3) * PAD + (idx & 7) * 4) = pc[q];
        }
        __syncthreads();

        // prefetch next chunk (overlaps with compute below)
        if (c + 1 < NCHUNK) {
            px0 = __ldg(xg0 + (c + 1) * 8);
            px1 = __ldg(xg1 + (c + 1) * 8);
            #pragma unroll
            for (int q = 0; q < 4; q++) {
                int idx = cidx0 + q * 128;
                if (idx < 440) {
                    int cl = idx >> 3, k4 = idx & 7;
                    pc[q] = __ldg((const float4*)(cen + (size_t)cl * DD)
                                  + (c + 1) * 8 + k4);
                }
            }
        }

        // compute: 8 k4-steps from smem
        #pragma unroll
        for (int k4 = 0; k4 < 8; k4++) {
            ulonglong2 b[7];
            #pragma unroll
            for (int j = 0; j < 7; j++) b[j] = bptr[j][k4];
            #pragma unroll
            for (int i = 0; i < 2; i++) {
                ulonglong2 a = aptr[i][k4];
                fma2(xn2[i], a.x, a.x);
                fma2(xn2[i], a.y, a.y);
                #pragma unroll
                for (int j = 0; j < 7; j++) {
                    fma2(acc[i][j], a.x, b[j].x);
                    fma2(acc[i][j], a.y, b[j].y);
                }
            }
        }
    }

    // ---- epilogue ----
    float cnv[7];
    int pres[7];
    #pragma unroll
    for (int j = 0; j < 7; j++) {
        if (cls[j] < NC) { cnv[j] = g_cn[cls[j]]; pres[j] = g_present[cls[j]]; }
        else             { cnv[j] = 0.0f;         pres[j] = 0; }
    }

    float lsum = 0.0f, psum = 0.0f;
    #pragma unroll
    for (int i = 0; i < 2; i++) {
        float xn = lo32(xn2[i]) + hi32(xn2[i]);
        int tg = tgt[r0 + mt * 2 + i];
        float ap = -1e30f, an = 1e30f;
        #pragma unroll
        for (int j = 0; j < 7; j++) {
            if (!pres[j]) continue;
            float S = lo32(acc[i][j]) + hi32(acc[i][j]);
            float d2 = xn + cnv[j] - 2.0f * S;
            float d = sqrtf(fmaxf(d2, 1e-12f));
            if (cls[j] == tg) ap = d;
            else an = fminf(an, d);
        }
        #pragma unroll
        for (int o = 1; o < 8; o <<= 1) {
            ap = fmaxf(ap, __shfl_xor_sync(0xffffffffu, ap, o));
            an = fminf(an, __shfl_xor_sync(0xffffffffu, an, o));
        }
        if (n == 0) {
            lsum += fmaxf(ap - an + MARGINF, 0.0f);
            psum += (an > ap) ? 1.0f : 0.0f;
        }
    }
    #pragma unroll
    for (int o = 16; o; o >>= 1) {
        lsum += __shfl_xor_sync(0xffffffffu, lsum, o);
        psum += __shfl_xor_sync(0xffffffffu, psum, o);
    }

    __shared__ float2 red[4];
    if ((tid & 31) == 0) red[tid >> 5] = make_float2(lsum, psum);
    __syncthreads();

    __shared__ int lastflag;
    if (tid == 0) {
        float a = 0.0f, b = 0.0f;
        #pragma unroll
        for (int w = 0; w < 4; w++) { a += red[w].x; b += red[w].y; }
        g_partial[blockIdx.x] = make_float2(a, b);
        __threadfence();
        int old = atomicAdd(&g_done, 1);
        lastflag = (old == (int)gridDim.x - 1) ? 1 : 0;
    }
    __syncthreads();

    if (lastflag) {
        __shared__ float2 s[128];
        float2 p0 = g_partial[tid];
        float2 p1 = g_partial[tid + 128];
        s[tid] = make_float2(p0.x + p1.x, p0.y + p1.y);
        __syncthreads();
        #pragma unroll
        for (int o = 64; o; o >>= 1) {
            if (tid < o) { s[tid].x += s[tid + o].x; s[tid].y += s[tid + o].y; }
            __syncthreads();
        }
        if (tid == 0) {
            out[0] = s[0].x / (float)BB;
            out[1] = s[0].y / (float)BB;
            g_done = 0;   // reset for graph replay
        }
    }
}

extern "C" void kernel_launch(void* const* d_in, const int* in_sizes, int n_in,
                              void* d_out, int out_size) {
    const float* x   = (const float*)d_in[0];
    const int*   tgt = (const int*)d_in[1];
    const float* cen = (const float*)d_in[2];
    float* out = (float*)d_out;

    prep_kernel<<<56, 256>>>(tgt, cen);
    tcl_main_kernel<<<256, 128>>>(x, tgt, cen, out);
}